// round 1
// baseline (speedup 1.0000x reference)
#include <cuda_runtime.h>
#include <math.h>

#define BATCH 8
#define SEQ 1024
#define HID 1024
#define NHEADS 16
#define DK 64

// ---------------- scratch (static __device__ — no allocs allowed) -------------
__device__ float g_yq[(size_t)BATCH * SEQ * HID];
__device__ float g_yk[(size_t)BATCH * SEQ * HID];
__device__ float g_yv[(size_t)BATCH * SEQ * HID];
__device__ float g_p[(size_t)BATCH * NHEADS * SEQ * SEQ];   // 512 MiB

// =============================================================================
// K1: projection GEMM  C[m,n] = sum_k A[m,k] * W[n,k]   (NT, row-major, fp32)
//     M=8192, N=1024, K=1024
// =============================================================================
namespace proj {
constexpr int BM = 128, BN = 128, BK = 16, TM = 8, TN = 8;  // 256 threads
}

__global__ void __launch_bounds__(256)
proj_gemm(const float* __restrict__ A, const float* __restrict__ W,
          float* __restrict__ C, int M, int N, int K)
{
    using namespace proj;
    __shared__ __align__(16) float As[BK][BM];
    __shared__ __align__(16) float Bs[BK][BN];

    const int tid = threadIdx.x;
    const int m0 = blockIdx.y * BM;
    const int n0 = blockIdx.x * BN;
    const int ty = tid / (BN / TN);   // 0..15
    const int tx = tid % (BN / TN);   // 0..15

    float acc[TM][TN];
#pragma unroll
    for (int i = 0; i < TM; i++)
#pragma unroll
        for (int j = 0; j < TN; j++) acc[i][j] = 0.f;

    for (int k0 = 0; k0 < K; k0 += BK) {
        // load A tile (BM x BK), transpose into As[k][m]
#pragma unroll
        for (int it = tid; it < BM * BK / 4; it += 256) {
            int lin = it * 4;
            int r = lin / BK, c = lin % BK;
            float4 t = *(const float4*)(A + (size_t)(m0 + r) * K + k0 + c);
            As[c + 0][r] = t.x; As[c + 1][r] = t.y;
            As[c + 2][r] = t.z; As[c + 3][r] = t.w;
        }
        // load W tile (BN x BK), transpose into Bs[k][n]
#pragma unroll
        for (int it = tid; it < BN * BK / 4; it += 256) {
            int lin = it * 4;
            int r = lin / BK, c = lin % BK;
            float4 t = *(const float4*)(W + (size_t)(n0 + r) * K + k0 + c);
            Bs[c + 0][r] = t.x; Bs[c + 1][r] = t.y;
            Bs[c + 2][r] = t.z; Bs[c + 3][r] = t.w;
        }
        __syncthreads();

#pragma unroll
        for (int kk = 0; kk < BK; kk++) {
            float ra[TM], rb[TN];
#pragma unroll
            for (int i = 0; i < TM; i++) ra[i] = As[kk][ty * TM + i];
#pragma unroll
            for (int j = 0; j < TN; j++) rb[j] = Bs[kk][tx * TN + j];
#pragma unroll
            for (int i = 0; i < TM; i++)
#pragma unroll
                for (int j = 0; j < TN; j++)
                    acc[i][j] += ra[i] * rb[j];
        }
        __syncthreads();
    }

#pragma unroll
    for (int i = 0; i < TM; i++) {
        int m = m0 + ty * TM + i;
#pragma unroll
        for (int j = 0; j < TN; j++)
            C[(size_t)m * N + n0 + tx * TN + j] = acc[i][j];
    }
}

// =============================================================================
// K2: per-head score GEMM  P[bh, jq, ik] = 0.125 * sum_d qh[jq,d] * kh[ik,d]
//     M = N = SEQ, K = DK = 64, lda = ldb = HID (head-strided views)
// =============================================================================
__global__ void __launch_bounds__(256)
score_gemm(const float* __restrict__ Yq, const float* __restrict__ Yk,
           float* __restrict__ P)
{
    constexpr int BM = 128, BN = 128, BK = 16, TM = 8, TN = 8;
    __shared__ __align__(16) float As[BK][BM];
    __shared__ __align__(16) float Bs[BK][BN];

    const int bh = blockIdx.z;
    const int b = bh / NHEADS, h = bh % NHEADS;
    const float* A = Yq + (size_t)b * SEQ * HID + h * DK;
    const float* Bm = Yk + (size_t)b * SEQ * HID + h * DK;
    float* C = g_p + (size_t)bh * SEQ * SEQ;

    const int tid = threadIdx.x;
    const int m0 = blockIdx.y * BM;
    const int n0 = blockIdx.x * BN;
    const int ty = tid / (BN / TN);
    const int tx = tid % (BN / TN);

    float acc[TM][TN];
#pragma unroll
    for (int i = 0; i < TM; i++)
#pragma unroll
        for (int j = 0; j < TN; j++) acc[i][j] = 0.f;

    for (int k0 = 0; k0 < DK; k0 += BK) {
#pragma unroll
        for (int it = tid; it < BM * BK / 4; it += 256) {
            int lin = it * 4;
            int r = lin / BK, c = lin % BK;
            float4 t = *(const float4*)(A + (size_t)(m0 + r) * HID + k0 + c);
            As[c + 0][r] = t.x; As[c + 1][r] = t.y;
            As[c + 2][r] = t.z; As[c + 3][r] = t.w;
        }
#pragma unroll
        for (int it = tid; it < BN * BK / 4; it += 256) {
            int lin = it * 4;
            int r = lin / BK, c = lin % BK;
            float4 t = *(const float4*)(Bm + (size_t)(n0 + r) * HID + k0 + c);
            Bs[c + 0][r] = t.x; Bs[c + 1][r] = t.y;
            Bs[c + 2][r] = t.z; Bs[c + 3][r] = t.w;
        }
        __syncthreads();

#pragma unroll
        for (int kk = 0; kk < BK; kk++) {
            float ra[TM], rb[TN];
#pragma unroll
            for (int i = 0; i < TM; i++) ra[i] = As[kk][ty * TM + i];
#pragma unroll
            for (int j = 0; j < TN; j++) rb[j] = Bs[kk][tx * TN + j];
#pragma unroll
            for (int i = 0; i < TM; i++)
#pragma unroll
                for (int j = 0; j < TN; j++)
                    acc[i][j] += ra[i] * rb[j];
        }
        __syncthreads();
    }

#pragma unroll
    for (int i = 0; i < TM; i++) {
        int m = m0 + ty * TM + i;
#pragma unroll
        for (int j = 0; j < TN; j++)
            C[(size_t)m * SEQ + n0 + tx * TN + j] = acc[i][j] * 0.125f;
    }
}

// =============================================================================
// K3: in-place row softmax over last axis. One block (256 thr) per row of 1024.
// =============================================================================
__global__ void __launch_bounds__(256)
softmax_rows(float* __restrict__ P)
{
    const size_t row = blockIdx.x;
    float* p = P + row * SEQ;
    const int tid = threadIdx.x;
    const int lane = tid & 31, wid = tid >> 5;

    float4 v = ((float4*)p)[tid];

    // max reduce
    float lm = fmaxf(fmaxf(v.x, v.y), fmaxf(v.z, v.w));
#pragma unroll
    for (int o = 16; o > 0; o >>= 1) lm = fmaxf(lm, __shfl_xor_sync(0xffffffffu, lm, o));
    __shared__ float sred[8];
    __shared__ float sbcast;
    if (lane == 0) sred[wid] = lm;
    __syncthreads();
    if (tid == 0) {
        float m = sred[0];
#pragma unroll
        for (int i = 1; i < 8; i++) m = fmaxf(m, sred[i]);
        sbcast = m;
    }
    __syncthreads();
    const float M = sbcast;

    v.x = expf(v.x - M); v.y = expf(v.y - M);
    v.z = expf(v.z - M); v.w = expf(v.w - M);

    float ls = v.x + v.y + v.z + v.w;
#pragma unroll
    for (int o = 16; o > 0; o >>= 1) ls += __shfl_xor_sync(0xffffffffu, ls, o);
    __syncthreads();
    if (lane == 0) sred[wid] = ls;
    __syncthreads();
    if (tid == 0) {
        float s = 0.f;
#pragma unroll
        for (int i = 0; i < 8; i++) s += sred[i];
        sbcast = 1.f / s;
    }
    __syncthreads();
    const float inv = sbcast;

    v.x *= inv; v.y *= inv; v.z *= inv; v.w *= inv;
    ((float4*)p)[tid] = v;
}

// =============================================================================
// K4: out[i,d] = sum_{j <= i} P[j,i] * vh[j,d]    (P^T @ V, triangular)
//     M = SEQ (i), N = DK (d), K = SEQ (j); mask only on diagonal tiles.
// =============================================================================
__global__ void __launch_bounds__(256)
out_gemm(const float* __restrict__ P, const float* __restrict__ Yv,
         float* __restrict__ Out)
{
    constexpr int BM = 64, BN = 64, BK = 32, TM = 8, TN = 2;
    // threads: (BM/TM)=8  x  (BN/TN)=32  = 256
    __shared__ __align__(16) float As[BK][BM];   // As[kk][i] = P[j0+kk][i0+i]
    __shared__ __align__(16) float Bs[BK][BN];   // Bs[kk][d] = V[j0+kk][d]

    const int bh = blockIdx.z;
    const int b = bh / NHEADS, h = bh % NHEADS;
    const float* Pm = P + (size_t)bh * SEQ * SEQ;
    const float* V  = Yv + (size_t)b * SEQ * HID + h * DK;
    float* O        = Out + (size_t)b * SEQ * HID + h * DK;

    const int i0 = blockIdx.x * BM;
    const int tid = threadIdx.x;
    const int ty = tid >> 5;          // 0..7   -> i sub-block
    const int tx = tid & 31;          // 0..31  -> d pair

    float acc[TM][TN];
#pragma unroll
    for (int i = 0; i < TM; i++) { acc[i][0] = 0.f; acc[i][1] = 0.f; }

    const int jend = i0 + BM;         // exclusive bound on j (j <= i_max = i0+BM-1)

    for (int j0 = 0; j0 < jend; j0 += BK) {
        // load P^T tile: rows j0..j0+31, cols i0..i0+63 (i-contiguous -> coalesced)
#pragma unroll
        for (int it = tid; it < BK * BM / 4; it += 256) {
            int lin = it * 4;
            int r = lin / BM, c = lin % BM;
            *(float4*)&As[r][c] =
                *(const float4*)(Pm + (size_t)(j0 + r) * SEQ + i0 + c);
        }
        // load V tile
#pragma unroll
        for (int it = tid; it < BK * BN / 4; it += 256) {
            int lin = it * 4;
            int r = lin / BN, c = lin % BN;
            *(float4*)&Bs[r][c] =
                *(const float4*)(V + (size_t)(j0 + r) * HID + c);
        }
        __syncthreads();

        const bool full = (j0 + BK - 1) <= i0;   // every j in tile <= every i in block
        if (full) {
#pragma unroll
            for (int kk = 0; kk < BK; kk++) {
                float2 rb = *(const float2*)&Bs[kk][tx * TN];
#pragma unroll
                for (int im = 0; im < TM; im++) {
                    float a = As[kk][ty * TM + im];
                    acc[im][0] += a * rb.x;
                    acc[im][1] += a * rb.y;
                }
            }
        } else {
            const int ibase = i0 + ty * TM;
#pragma unroll
            for (int kk = 0; kk < BK; kk++) {
                const int j = j0 + kk;
                float2 rb = *(const float2*)&Bs[kk][tx * TN];
#pragma unroll
                for (int im = 0; im < TM; im++) {
                    if (j <= ibase + im) {
                        float a = As[kk][ty * TM + im];
                        acc[im][0] += a * rb.x;
                        acc[im][1] += a * rb.y;
                    }
                }
            }
        }
        __syncthreads();
    }

#pragma unroll
    for (int im = 0; im < TM; im++) {
        int i = i0 + ty * TM + im;
#pragma unroll
        for (int jn = 0; jn < TN; jn++)
            O[(size_t)i * HID + tx * TN + jn] = acc[im][jn];
    }
}

// =============================================================================
extern "C" void kernel_launch(void* const* d_in, const int* in_sizes, int n_in,
                              void* d_out, int out_size)
{
    const float* q  = (const float*)d_in[0];
    const float* k  = (const float*)d_in[1];
    const float* v  = (const float*)d_in[2];
    const float* Wq = (const float*)d_in[3];
    const float* Wk = (const float*)d_in[4];
    const float* Wv = (const float*)d_in[5];
    float* out = (float*)d_out;
    (void)in_sizes; (void)n_in; (void)out_size;

    float *yq, *yk, *yv, *p;
    cudaGetSymbolAddress((void**)&yq, g_yq);
    cudaGetSymbolAddress((void**)&yk, g_yk);
    cudaGetSymbolAddress((void**)&yv, g_yv);
    cudaGetSymbolAddress((void**)&p,  g_p);

    const int M = BATCH * SEQ;      // 8192
    dim3 pgrid(HID / proj::BN, M / proj::BM);   // (8, 64)
    proj_gemm<<<pgrid, 256>>>(q, Wq, yq, M, HID, HID);
    proj_gemm<<<pgrid, 256>>>(k, Wk, yk, M, HID, HID);
    proj_gemm<<<pgrid, 256>>>(v, Wv, yv, M, HID, HID);

    dim3 sgrid(SEQ / 128, SEQ / 128, BATCH * NHEADS);   // (8, 8, 128)
    score_gemm<<<sgrid, 256>>>(yq, yk, p);

    softmax_rows<<<(unsigned)((size_t)BATCH * NHEADS * SEQ), 256>>>(p);

    dim3 ogrid(SEQ / 64, 1, BATCH * NHEADS);            // (16, 1, 128)
    out_gemm<<<ogrid, 256>>>(p, yv, out);
}

// round 5
// speedup vs baseline: 2.2835x; 2.2835x over previous
#include <cuda_runtime.h>
#include <cuda_bf16.h>
#include <stdint.h>
#include <math.h>

#define BATCH 8
#define SEQ 1024
#define HID 1024
#define NHEADS 16
#define DK 64

// ---------------- scratch (static __device__ — no allocs allowed) -------------
__device__ __align__(16) __nv_bfloat16 g_yqh[8192 * 1024];
__device__ __align__(16) __nv_bfloat16 g_yql[8192 * 1024];
__device__ __align__(16) __nv_bfloat16 g_ykh[8192 * 1024];
__device__ __align__(16) __nv_bfloat16 g_ykl[8192 * 1024];
__device__ __align__(16) __nv_bfloat16 g_yvh[8192 * 1024];
__device__ __align__(16) __nv_bfloat16 g_yvl[8192 * 1024];
__device__ __align__(16) float         g_pf[134217728];     // 512 MiB fp32 scores
__device__ __align__(16) __nv_bfloat16 g_ph[134217728];     // 256 MiB softmaxed+masked hi
__device__ __align__(16) __nv_bfloat16 g_pl[134217728];     // 256 MiB lo

// ---------------- helpers ----------------------------------------------------
__device__ __forceinline__ uint32_t saddr_of(const void* p) {
    return (uint32_t)__cvta_generic_to_shared(p);
}
__device__ __forceinline__ void ldsm4(uint32_t r[4], uint32_t a) {
    asm volatile("ldmatrix.sync.aligned.m8n8.x4.shared.b16 {%0,%1,%2,%3}, [%4];"
                 : "=r"(r[0]), "=r"(r[1]), "=r"(r[2]), "=r"(r[3]) : "r"(a));
}
__device__ __forceinline__ void ldsm4t(uint32_t r[4], uint32_t a) {
    asm volatile("ldmatrix.sync.aligned.m8n8.x4.trans.shared.b16 {%0,%1,%2,%3}, [%4];"
                 : "=r"(r[0]), "=r"(r[1]), "=r"(r[2]), "=r"(r[3]) : "r"(a));
}
__device__ __forceinline__ void mma16816(float* c, const uint32_t* a, const uint32_t* b) {
    asm volatile("mma.sync.aligned.m16n8k16.row.col.f32.bf16.bf16.f32 "
                 "{%0,%1,%2,%3}, {%4,%5,%6,%7}, {%8,%9}, {%0,%1,%2,%3};"
                 : "+f"(c[0]), "+f"(c[1]), "+f"(c[2]), "+f"(c[3])
                 : "r"(a[0]), "r"(a[1]), "r"(a[2]), "r"(a[3]), "r"(b[0]), "r"(b[1]));
}
__device__ __forceinline__ void split2(float x, __nv_bfloat16& h, __nv_bfloat16& l) {
    h = __float2bfloat16(x);
    l = __float2bfloat16(x - __bfloat162float(h));
}

// =============================================================================
// K1: projection  Y[m,n] = sum_k A[m,k] * W[n,k]   (M=8192, N=K=1024)
//     fp32 in, split-bf16 (hi/lo) out.  Block 128x128, BK=32, 8 warps (64x32).
// =============================================================================
__global__ void __launch_bounds__(256)
proj_mma(const float* __restrict__ A, const float* __restrict__ W,
         __nv_bfloat16* __restrict__ Yh, __nv_bfloat16* __restrict__ Yl)
{
    __shared__ __align__(16) __nv_bfloat16 Ah[128][40];
    __shared__ __align__(16) __nv_bfloat16 Al[128][40];
    __shared__ __align__(16) __nv_bfloat16 Bh[128][40];
    __shared__ __align__(16) __nv_bfloat16 Bl[128][40];

    const int tid = threadIdx.x;
    const int lane = tid & 31;
    const int w = tid >> 5;
    const int wm = w >> 2, wn = w & 3;
    const int m0 = blockIdx.y * 128, n0 = blockIdx.x * 128;
    const int lr = tid >> 3, lc = tid & 7;

    float acc[4][4][4] = {};

    float4 pa[4], pb[4];
#pragma unroll
    for (int q = 0; q < 4; q++) {
        pa[q] = *(const float4*)(A + (size_t)(m0 + lr + q * 32) * 1024 + lc * 4);
        pb[q] = *(const float4*)(W + (size_t)(n0 + lr + q * 32) * 1024 + lc * 4);
    }

    for (int k0 = 0; k0 < 1024; k0 += 32) {
        // split-convert prefetched regs into smem
#pragma unroll
        for (int q = 0; q < 4; q++) {
            int r = lr + q * 32;
            float va[4] = {pa[q].x, pa[q].y, pa[q].z, pa[q].w};
            float vb[4] = {pb[q].x, pb[q].y, pb[q].z, pb[q].w};
            __nv_bfloat16 ha[4], la[4], hb[4], lb[4];
#pragma unroll
            for (int e = 0; e < 4; e++) {
                split2(va[e], ha[e], la[e]);
                split2(vb[e], hb[e], lb[e]);
            }
            *(__nv_bfloat162*)&Ah[r][lc * 4]     = __halves2bfloat162(ha[0], ha[1]);
            *(__nv_bfloat162*)&Ah[r][lc * 4 + 2] = __halves2bfloat162(ha[2], ha[3]);
            *(__nv_bfloat162*)&Al[r][lc * 4]     = __halves2bfloat162(la[0], la[1]);
            *(__nv_bfloat162*)&Al[r][lc * 4 + 2] = __halves2bfloat162(la[2], la[3]);
            *(__nv_bfloat162*)&Bh[r][lc * 4]     = __halves2bfloat162(hb[0], hb[1]);
            *(__nv_bfloat162*)&Bh[r][lc * 4 + 2] = __halves2bfloat162(hb[2], hb[3]);
            *(__nv_bfloat162*)&Bl[r][lc * 4]     = __halves2bfloat162(lb[0], lb[1]);
            *(__nv_bfloat162*)&Bl[r][lc * 4 + 2] = __halves2bfloat162(lb[2], lb[3]);
        }
        __syncthreads();

        if (k0 + 32 < 1024) {
#pragma unroll
            for (int q = 0; q < 4; q++) {
                pa[q] = *(const float4*)(A + (size_t)(m0 + lr + q * 32) * 1024 + (k0 + 32) + lc * 4);
                pb[q] = *(const float4*)(W + (size_t)(n0 + lr + q * 32) * 1024 + (k0 + 32) + lc * 4);
            }
        }

#pragma unroll
        for (int ks = 0; ks < 32; ks += 16) {
            uint32_t ah[4][4], al[4][4], bh[4][2], bl[4][2];
#pragma unroll
            for (int mt = 0; mt < 4; mt++) {
                int row = wm * 64 + mt * 16 + (lane & 15);
                int col = ks + ((lane >> 4) << 3);
                ldsm4(ah[mt], saddr_of(&Ah[row][col]));
                ldsm4(al[mt], saddr_of(&Al[row][col]));
            }
#pragma unroll
            for (int p = 0; p < 2; p++) {
                int row = wn * 32 + p * 16 + ((lane >> 4) << 3) + (lane & 7);
                int col = ks + (((lane >> 3) & 1) << 3);
                uint32_t t4[4];
                ldsm4(t4, saddr_of(&Bh[row][col]));
                bh[p * 2][0] = t4[0]; bh[p * 2][1] = t4[1];
                bh[p * 2 + 1][0] = t4[2]; bh[p * 2 + 1][1] = t4[3];
                ldsm4(t4, saddr_of(&Bl[row][col]));
                bl[p * 2][0] = t4[0]; bl[p * 2][1] = t4[1];
                bl[p * 2 + 1][0] = t4[2]; bl[p * 2 + 1][1] = t4[3];
            }
#pragma unroll
            for (int mt = 0; mt < 4; mt++)
#pragma unroll
                for (int nt = 0; nt < 4; nt++) {
                    mma16816(acc[mt][nt], ah[mt], bh[nt]);
                    mma16816(acc[mt][nt], ah[mt], bl[nt]);
                    mma16816(acc[mt][nt], al[mt], bh[nt]);
                }
        }
        __syncthreads();
    }

    const int gr = lane >> 2, gc = (lane & 3) << 1;
#pragma unroll
    for (int mt = 0; mt < 4; mt++)
#pragma unroll
        for (int nt = 0; nt < 4; nt++) {
            int m = m0 + wm * 64 + mt * 16 + gr;
            int n = n0 + wn * 32 + nt * 8 + gc;
#pragma unroll
            for (int hf = 0; hf < 2; hf++) {
                float c0 = acc[mt][nt][hf * 2], c1 = acc[mt][nt][hf * 2 + 1];
                __nv_bfloat16 h0, l0, h1, l1;
                split2(c0, h0, l0);
                split2(c1, h1, l1);
                size_t off = (size_t)(m + hf * 8) * 1024 + n;
                *(__nv_bfloat162*)(Yh + off) = __halves2bfloat162(h0, h1);
                *(__nv_bfloat162*)(Yl + off) = __halves2bfloat162(l0, l1);
            }
        }
}

// =============================================================================
// K2: score  P[bh, q, i] = 0.125 * sum_d qh[q,d]*kh[i,d]
//     split-bf16 in, fp32 out.  Block 128x128, K chunked 2x32, static 40KB smem.
// =============================================================================
__global__ void __launch_bounds__(256)
score_mma(const __nv_bfloat16* __restrict__ Qh, const __nv_bfloat16* __restrict__ Ql,
          const __nv_bfloat16* __restrict__ Kh, const __nv_bfloat16* __restrict__ Kl,
          float* __restrict__ Pf)
{
    __shared__ __align__(16) __nv_bfloat16 Ah[128][40];
    __shared__ __align__(16) __nv_bfloat16 Al[128][40];
    __shared__ __align__(16) __nv_bfloat16 Bh[128][40];
    __shared__ __align__(16) __nv_bfloat16 Bl[128][40];

    const int tid = threadIdx.x, lane = tid & 31, w = tid >> 5;
    const int wm = w >> 2, wn = w & 3;
    const int bhz = blockIdx.z, b = bhz >> 4, h = bhz & 15;
    const int m0 = blockIdx.y * 128, n0 = blockIdx.x * 128;

    const size_t qbase = (size_t)(b * 1024 + m0) * 1024 + h * 64;
    const size_t kbase = (size_t)(b * 1024 + n0) * 1024 + h * 64;

    float acc[4][4][4] = {};

    for (int k0 = 0; k0 < 64; k0 += 32) {
#pragma unroll
        for (int it = 0; it < 2; it++) {
            int id = tid + it * 256;
            int r = id >> 2, c = (id & 3) * 8;
            *(uint4*)&Ah[r][c] = *(const uint4*)(Qh + qbase + (size_t)r * 1024 + k0 + c);
            *(uint4*)&Al[r][c] = *(const uint4*)(Ql + qbase + (size_t)r * 1024 + k0 + c);
            *(uint4*)&Bh[r][c] = *(const uint4*)(Kh + kbase + (size_t)r * 1024 + k0 + c);
            *(uint4*)&Bl[r][c] = *(const uint4*)(Kl + kbase + (size_t)r * 1024 + k0 + c);
        }
        __syncthreads();

#pragma unroll
        for (int ks = 0; ks < 32; ks += 16) {
            uint32_t ah[4][4], al[4][4], bh[4][2], bl[4][2];
#pragma unroll
            for (int mt = 0; mt < 4; mt++) {
                int row = wm * 64 + mt * 16 + (lane & 15);
                int col = ks + ((lane >> 4) << 3);
                ldsm4(ah[mt], saddr_of(&Ah[row][col]));
                ldsm4(al[mt], saddr_of(&Al[row][col]));
            }
#pragma unroll
            for (int p = 0; p < 2; p++) {
                int row = wn * 32 + p * 16 + ((lane >> 4) << 3) + (lane & 7);
                int col = ks + (((lane >> 3) & 1) << 3);
                uint32_t t4[4];
                ldsm4(t4, saddr_of(&Bh[row][col]));
                bh[p * 2][0] = t4[0]; bh[p * 2][1] = t4[1];
                bh[p * 2 + 1][0] = t4[2]; bh[p * 2 + 1][1] = t4[3];
                ldsm4(t4, saddr_of(&Bl[row][col]));
                bl[p * 2][0] = t4[0]; bl[p * 2][1] = t4[1];
                bl[p * 2 + 1][0] = t4[2]; bl[p * 2 + 1][1] = t4[3];
            }
#pragma unroll
            for (int mt = 0; mt < 4; mt++)
#pragma unroll
                for (int nt = 0; nt < 4; nt++) {
                    mma16816(acc[mt][nt], ah[mt], bh[nt]);
                    mma16816(acc[mt][nt], ah[mt], bl[nt]);
                    mma16816(acc[mt][nt], al[mt], bh[nt]);
                }
        }
        __syncthreads();
    }

    float* P = Pf + ((size_t)bhz << 20);
    const int gr = lane >> 2, gc = (lane & 3) << 1;
#pragma unroll
    for (int mt = 0; mt < 4; mt++)
#pragma unroll
        for (int nt = 0; nt < 4; nt++) {
            int m = m0 + wm * 64 + mt * 16 + gr;
            int n = n0 + wn * 32 + nt * 8 + gc;
#pragma unroll
            for (int hf = 0; hf < 2; hf++) {
                *(float2*)(P + (size_t)(m + hf * 8) * 1024 + n) =
                    make_float2(acc[mt][nt][hf * 2] * 0.125f, acc[mt][nt][hf * 2 + 1] * 0.125f);
            }
        }
}

// =============================================================================
// K3: softmax over row (axis i), then mask (keep i >= j), then split-bf16 out.
//     grid = BATCH*NHEADS*SEQ = 1<<17 rows.
// =============================================================================
__global__ void __launch_bounds__(256)
softmax_mask_split(const float* __restrict__ Pf, __nv_bfloat16* __restrict__ Ph,
                   __nv_bfloat16* __restrict__ Pl)
{
    const size_t rid = blockIdx.x;
    const float* p = Pf + (rid << 10);
    const int j = (int)(rid & 1023);
    const int tid = threadIdx.x, lane = tid & 31, wid = tid >> 5;

    float4 v = ((const float4*)p)[tid];

    float lm = fmaxf(fmaxf(v.x, v.y), fmaxf(v.z, v.w));
#pragma unroll
    for (int o = 16; o > 0; o >>= 1) lm = fmaxf(lm, __shfl_xor_sync(0xffffffffu, lm, o));
    __shared__ float sred[8];
    __shared__ float sb;
    if (lane == 0) sred[wid] = lm;
    __syncthreads();
    if (tid == 0) {
        float m = sred[0];
#pragma unroll
        for (int i = 1; i < 8; i++) m = fmaxf(m, sred[i]);
        sb = m;
    }
    __syncthreads();
    const float M = sb;

    v.x = __expf(v.x - M); v.y = __expf(v.y - M);
    v.z = __expf(v.z - M); v.w = __expf(v.w - M);

    float ls = v.x + v.y + v.z + v.w;
#pragma unroll
    for (int o = 16; o > 0; o >>= 1) ls += __shfl_xor_sync(0xffffffffu, ls, o);
    __syncthreads();
    if (lane == 0) sred[wid] = ls;
    __syncthreads();
    if (tid == 0) {
        float s = 0.f;
#pragma unroll
        for (int i = 0; i < 8; i++) s += sred[i];
        sb = 1.f / s;
    }
    __syncthreads();
    const float inv = sb;

    const int i0 = tid * 4;
    float r[4] = {v.x, v.y, v.z, v.w};
    __nv_bfloat16 h[4], l[4];
#pragma unroll
    for (int e = 0; e < 4; e++) {
        float x = (i0 + e >= j) ? r[e] * inv : 0.f;   // post-softmax triangular mask
        split2(x, h[e], l[e]);
    }
    *(__nv_bfloat162*)(Ph + (rid << 10) + i0)     = __halves2bfloat162(h[0], h[1]);
    *(__nv_bfloat162*)(Ph + (rid << 10) + i0 + 2) = __halves2bfloat162(h[2], h[3]);
    *(__nv_bfloat162*)(Pl + (rid << 10) + i0)     = __halves2bfloat162(l[0], l[1]);
    *(__nv_bfloat162*)(Pl + (rid << 10) + i0 + 2) = __halves2bfloat162(l[2], l[3]);
}

// =============================================================================
// K4: out[i,d] = sum_j P[j,i] * vh[j,d]   (dense now — mask already in P)
//     A = P^T via ldmatrix.trans, B = V via ldmatrix.trans. Skip tiles j > i.
//     Block 128(i) x 64(d), BK=32, 8 warps (32x32).
// =============================================================================
__global__ void __launch_bounds__(256)
out_mma(const __nv_bfloat16* __restrict__ Ph, const __nv_bfloat16* __restrict__ Pl,
        const __nv_bfloat16* __restrict__ Vh, const __nv_bfloat16* __restrict__ Vl,
        float* __restrict__ Out)
{
    __shared__ __align__(16) __nv_bfloat16 Psh[32][136];
    __shared__ __align__(16) __nv_bfloat16 Psl[32][136];
    __shared__ __align__(16) __nv_bfloat16 Vsh[32][72];
    __shared__ __align__(16) __nv_bfloat16 Vsl[32][72];

    const int tid = threadIdx.x, lane = tid & 31, w = tid >> 5;
    const int wm = w >> 1, wn = w & 1;
    const int bhz = blockIdx.z, b = bhz >> 4, h = bhz & 15;
    const int i0 = blockIdx.x * 128;

    const __nv_bfloat16* Pbh = Ph + ((size_t)bhz << 20);
    const __nv_bfloat16* Pbl = Pl + ((size_t)bhz << 20);

    float acc[2][4][4] = {};

    const int pr = tid >> 4, pc = tid & 15;
    const int vr = tid >> 3, vc = tid & 7;

    const int jend = i0 + 128;
    for (int j0 = 0; j0 < jend; j0 += 32) {
#pragma unroll
        for (int q = 0; q < 2; q++) {
            int r = pr + q * 16;
            *(uint4*)&Psh[r][pc * 8] = *(const uint4*)(Pbh + (size_t)(j0 + r) * 1024 + i0 + pc * 8);
            *(uint4*)&Psl[r][pc * 8] = *(const uint4*)(Pbl + (size_t)(j0 + r) * 1024 + i0 + pc * 8);
        }
        {
            size_t vb = (size_t)(b * 1024 + j0 + vr) * 1024 + h * 64 + vc * 8;
            *(uint4*)&Vsh[vr][vc * 8] = *(const uint4*)(Vh + vb);
            *(uint4*)&Vsl[vr][vc * 8] = *(const uint4*)(Vl + vb);
        }
        __syncthreads();

#pragma unroll
        for (int ks = 0; ks < 32; ks += 16) {
            uint32_t ah[2][4], al[2][4], bh[4][2], bl[4][2];
#pragma unroll
            for (int mt = 0; mt < 2; mt++) {
                int jr = ks + (lane & 7) + ((lane >> 4) << 3);
                int ic = wm * 32 + mt * 16 + (((lane >> 3) & 1) << 3);
                ldsm4t(ah[mt], saddr_of(&Psh[jr][ic]));
                ldsm4t(al[mt], saddr_of(&Psl[jr][ic]));
            }
#pragma unroll
            for (int p = 0; p < 2; p++) {
                int kr = ks + (((lane >> 3) & 1) << 3) + (lane & 7);
                int dc = wn * 32 + p * 16 + ((lane >> 4) << 3);
                uint32_t t4[4];
                ldsm4t(t4, saddr_of(&Vsh[kr][dc]));
                bh[p * 2][0] = t4[0]; bh[p * 2][1] = t4[1];
                bh[p * 2 + 1][0] = t4[2]; bh[p * 2 + 1][1] = t4[3];
                ldsm4t(t4, saddr_of(&Vsl[kr][dc]));
                bl[p * 2][0] = t4[0]; bl[p * 2][1] = t4[1];
                bl[p * 2 + 1][0] = t4[2]; bl[p * 2 + 1][1] = t4[3];
            }
#pragma unroll
            for (int mt = 0; mt < 2; mt++)
#pragma unroll
                for (int nt = 0; nt < 4; nt++) {
                    mma16816(acc[mt][nt], ah[mt], bh[nt]);
                    mma16816(acc[mt][nt], ah[mt], bl[nt]);
                    mma16816(acc[mt][nt], al[mt], bh[nt]);
                }
        }
        __syncthreads();
    }

    const int gr = lane >> 2, gc = (lane & 3) << 1;
#pragma unroll
    for (int mt = 0; mt < 2; mt++)
#pragma unroll
        for (int nt = 0; nt < 4; nt++) {
            int i = i0 + wm * 32 + mt * 16 + gr;
            int d = wn * 32 + nt * 8 + gc;
#pragma unroll
            for (int hf = 0; hf < 2; hf++) {
                *(float2*)(Out + (size_t)(b * 1024 + i + hf * 8) * 1024 + h * 64 + d) =
                    make_float2(acc[mt][nt][hf * 2], acc[mt][nt][hf * 2 + 1]);
            }
        }
}

// =============================================================================
extern "C" void kernel_launch(void* const* d_in, const int* in_sizes, int n_in,
                              void* d_out, int out_size)
{
    const float* q  = (const float*)d_in[0];
    const float* k  = (const float*)d_in[1];
    const float* v  = (const float*)d_in[2];
    const float* Wq = (const float*)d_in[3];
    const float* Wk = (const float*)d_in[4];
    const float* Wv = (const float*)d_in[5];
    float* out = (float*)d_out;
    (void)in_sizes; (void)n_in; (void)out_size;

    __nv_bfloat16 *yqh, *yql, *ykh, *ykl, *yvh, *yvl, *ph, *pl;
    float* pf;
    cudaGetSymbolAddress((void**)&yqh, g_yqh);
    cudaGetSymbolAddress((void**)&yql, g_yql);
    cudaGetSymbolAddress((void**)&ykh, g_ykh);
    cudaGetSymbolAddress((void**)&ykl, g_ykl);
    cudaGetSymbolAddress((void**)&yvh, g_yvh);
    cudaGetSymbolAddress((void**)&yvl, g_yvl);
    cudaGetSymbolAddress((void**)&pf,  g_pf);
    cudaGetSymbolAddress((void**)&ph,  g_ph);
    cudaGetSymbolAddress((void**)&pl,  g_pl);

    dim3 pgrid(8, 64);
    proj_mma<<<pgrid, 256>>>(q, Wq, yqh, yql);
    proj_mma<<<pgrid, 256>>>(k, Wk, ykh, ykl);
    proj_mma<<<pgrid, 256>>>(v, Wv, yvh, yvl);

    dim3 sgrid(8, 8, BATCH * NHEADS);
    score_mma<<<sgrid, 256>>>(yqh, yql, ykh, ykl, pf);

    // rows = BATCH*NHEADS*SEQ = 1<<17  (Round-3 bug: was 1<<20 -> OOB reads)
    softmax_mask_split<<<BATCH * NHEADS * SEQ, 256>>>(pf, ph, pl);

    dim3 ogrid(8, 1, BATCH * NHEADS);
    out_mma<<<ogrid, 256>>>(ph, pl, yvh, yvl, out);
}

// round 6
// speedup vs baseline: 2.7331x; 1.1969x over previous
#include <cuda_runtime.h>
#include <cuda_bf16.h>
#include <stdint.h>

#define BATCH 8
#define SEQ 1024
#define HID 1024
#define NHEADS 16
#define DK 64

#define XN 8388608   // 8192*1024
#define WN 1048576   // 1024*1024

// ---------------- scratch (static __device__ — no allocs allowed) -------------
__device__ __align__(16) __nv_bfloat16 g_xh[3 * XN];   // pre-split q,k,v hi
__device__ __align__(16) __nv_bfloat16 g_xl[3 * XN];
__device__ __align__(16) __nv_bfloat16 g_wh[3 * WN];   // pre-split Wq,Wk,Wv hi
__device__ __align__(16) __nv_bfloat16 g_wl[3 * WN];
__device__ __align__(16) __nv_bfloat16 g_yh[3 * XN];   // projected q,k,v hi
__device__ __align__(16) __nv_bfloat16 g_yl[3 * XN];
__device__ __align__(16) float         g_pf[134217728];  // fp32 scores
__device__ __align__(16) __nv_bfloat16 g_ph[134217728];  // softmaxed+masked hi
__device__ __align__(16) __nv_bfloat16 g_pl[134217728];  // lo

// ---------------- helpers ----------------------------------------------------
__device__ __forceinline__ uint32_t saddr_of(const void* p) {
    return (uint32_t)__cvta_generic_to_shared(p);
}
__device__ __forceinline__ void cpa16(uint32_t dst, const void* src) {
    asm volatile("cp.async.cg.shared.global [%0], [%1], 16;" :: "r"(dst), "l"(src));
}
__device__ __forceinline__ void cpa_commit() {
    asm volatile("cp.async.commit_group;");
}
template <int N>
__device__ __forceinline__ void cpa_wait() {
    asm volatile("cp.async.wait_group %0;" :: "n"(N));
}
__device__ __forceinline__ void ldsm4(uint32_t r[4], uint32_t a) {
    asm volatile("ldmatrix.sync.aligned.m8n8.x4.shared.b16 {%0,%1,%2,%3}, [%4];"
                 : "=r"(r[0]), "=r"(r[1]), "=r"(r[2]), "=r"(r[3]) : "r"(a));
}
__device__ __forceinline__ void ldsm4t(uint32_t r[4], uint32_t a) {
    asm volatile("ldmatrix.sync.aligned.m8n8.x4.trans.shared.b16 {%0,%1,%2,%3}, [%4];"
                 : "=r"(r[0]), "=r"(r[1]), "=r"(r[2]), "=r"(r[3]) : "r"(a));
}
__device__ __forceinline__ void mma16816(float* c, const uint32_t* a, const uint32_t* b) {
    asm volatile("mma.sync.aligned.m16n8k16.row.col.f32.bf16.bf16.f32 "
                 "{%0,%1,%2,%3}, {%4,%5,%6,%7}, {%8,%9}, {%0,%1,%2,%3};"
                 : "+f"(c[0]), "+f"(c[1]), "+f"(c[2]), "+f"(c[3])
                 : "r"(a[0]), "r"(a[1]), "r"(a[2]), "r"(a[3]), "r"(b[0]), "r"(b[1]));
}
__device__ __forceinline__ void split2(float x, __nv_bfloat16& h, __nv_bfloat16& l) {
    h = __float2bfloat16(x);
    l = __float2bfloat16(x - __bfloat162float(h));
}

// =============================================================================
// K0: elementwise fp32 -> split bf16 hi/lo.  4 elems/thread, exact-sized grid.
// =============================================================================
__global__ void __launch_bounds__(256)
split_kernel(const float* __restrict__ X, __nv_bfloat16* __restrict__ H,
             __nv_bfloat16* __restrict__ L)
{
    size_t i = ((size_t)blockIdx.x * 256 + threadIdx.x) * 4;
    float4 v = *(const float4*)(X + i);
    __nv_bfloat16 h[4], l[4];
    split2(v.x, h[0], l[0]); split2(v.y, h[1], l[1]);
    split2(v.z, h[2], l[2]); split2(v.w, h[3], l[3]);
    *(__nv_bfloat162*)(H + i)     = __halves2bfloat162(h[0], h[1]);
    *(__nv_bfloat162*)(H + i + 2) = __halves2bfloat162(h[2], h[3]);
    *(__nv_bfloat162*)(L + i)     = __halves2bfloat162(l[0], l[1]);
    *(__nv_bfloat162*)(L + i + 2) = __halves2bfloat162(l[2], l[3]);
}

// =============================================================================
// K1: projection  Y[m,n] = sum_k X[m,k] * W[n,k]   (M=8192, N=K=1024, z=q/k/v)
//     split-bf16 in (pre-split), split-bf16 out.
//     Block 128x128, BK=32, cp.async 2-stage pipeline, 80KB dyn smem.
// =============================================================================
__global__ void __launch_bounds__(256)
proj_mma(const __nv_bfloat16* __restrict__ Xh, const __nv_bfloat16* __restrict__ Xl,
         const __nv_bfloat16* __restrict__ Wh, const __nv_bfloat16* __restrict__ Wl,
         __nv_bfloat16* __restrict__ Yh, __nv_bfloat16* __restrict__ Yl)
{
    extern __shared__ __align__(16) __nv_bfloat16 smem[];
    // per stage (20480 elems): Ah[128][40] @0, Al @5120, Bh @10240, Bl @15360

    const int tid = threadIdx.x, lane = tid & 31, w = tid >> 5;
    const int wm = w >> 2, wn = w & 3;
    const int z = blockIdx.z;
    const size_t xoff = (size_t)z * XN, woff = (size_t)z * WN;
    Xh += xoff; Xl += xoff; Yh += xoff; Yl += xoff; Wh += woff; Wl += woff;
    const int m0 = blockIdx.y * 128, n0 = blockIdx.x * 128;

    const int lr = tid >> 2, lc = (tid & 3) * 8;   // 64 rows/pass, 2 passes

    float acc[4][4][4] = {};

#define STG(s, off) (smem + (s) * 20480 + (off))

    auto load_stage = [&](int s, int k0) {
#pragma unroll
        for (int q = 0; q < 2; q++) {
            int r = lr + q * 64;
            cpa16(saddr_of(STG(s, 0)     + r * 40 + lc), Xh + (size_t)(m0 + r) * 1024 + k0 + lc);
            cpa16(saddr_of(STG(s, 5120)  + r * 40 + lc), Xl + (size_t)(m0 + r) * 1024 + k0 + lc);
            cpa16(saddr_of(STG(s, 10240) + r * 40 + lc), Wh + (size_t)(n0 + r) * 1024 + k0 + lc);
            cpa16(saddr_of(STG(s, 15360) + r * 40 + lc), Wl + (size_t)(n0 + r) * 1024 + k0 + lc);
        }
    };

    load_stage(0, 0);
    cpa_commit();

    for (int it = 0; it < 32; it++) {
        const int cur = it & 1;
        if (it + 1 < 32) {
            load_stage(cur ^ 1, (it + 1) * 32);
            cpa_commit();
            cpa_wait<1>();
        } else {
            cpa_wait<0>();
        }
        __syncthreads();

        const __nv_bfloat16* Ah = STG(cur, 0);
        const __nv_bfloat16* Al = STG(cur, 5120);
        const __nv_bfloat16* Bh = STG(cur, 10240);
        const __nv_bfloat16* Bl = STG(cur, 15360);

#pragma unroll
        for (int ks = 0; ks < 32; ks += 16) {
            uint32_t ah[4][4], al[4][4], bh[4][2], bl[4][2];
#pragma unroll
            for (int mt = 0; mt < 4; mt++) {
                int row = wm * 64 + mt * 16 + (lane & 15);
                int col = ks + ((lane >> 4) << 3);
                ldsm4(ah[mt], saddr_of(Ah + row * 40 + col));
                ldsm4(al[mt], saddr_of(Al + row * 40 + col));
            }
#pragma unroll
            for (int p = 0; p < 2; p++) {
                int row = wn * 32 + p * 16 + ((lane >> 4) << 3) + (lane & 7);
                int col = ks + (((lane >> 3) & 1) << 3);
                uint32_t t4[4];
                ldsm4(t4, saddr_of(Bh + row * 40 + col));
                bh[p * 2][0] = t4[0]; bh[p * 2][1] = t4[1];
                bh[p * 2 + 1][0] = t4[2]; bh[p * 2 + 1][1] = t4[3];
                ldsm4(t4, saddr_of(Bl + row * 40 + col));
                bl[p * 2][0] = t4[0]; bl[p * 2][1] = t4[1];
                bl[p * 2 + 1][0] = t4[2]; bl[p * 2 + 1][1] = t4[3];
            }
#pragma unroll
            for (int mt = 0; mt < 4; mt++)
#pragma unroll
                for (int nt = 0; nt < 4; nt++) {
                    mma16816(acc[mt][nt], ah[mt], bh[nt]);
                    mma16816(acc[mt][nt], ah[mt], bl[nt]);
                    mma16816(acc[mt][nt], al[mt], bh[nt]);
                }
        }
        __syncthreads();
    }
#undef STG

    const int gr = lane >> 2, gc = (lane & 3) << 1;
#pragma unroll
    for (int mt = 0; mt < 4; mt++)
#pragma unroll
        for (int nt = 0; nt < 4; nt++) {
            int m = m0 + wm * 64 + mt * 16 + gr;
            int n = n0 + wn * 32 + nt * 8 + gc;
#pragma unroll
            for (int hf = 0; hf < 2; hf++) {
                float c0 = acc[mt][nt][hf * 2], c1 = acc[mt][nt][hf * 2 + 1];
                __nv_bfloat16 h0, l0, h1, l1;
                split2(c0, h0, l0);
                split2(c1, h1, l1);
                size_t off = (size_t)(m + hf * 8) * 1024 + n;
                *(__nv_bfloat162*)(Yh + off) = __halves2bfloat162(h0, h1);
                *(__nv_bfloat162*)(Yl + off) = __halves2bfloat162(l0, l1);
            }
        }
}

// =============================================================================
// K2: score  P[bh, q, i] = 0.125 * sum_d qh[q,d]*kh[i,d]
//     whole K=64 in one cp.async batch, 72KB dyn smem, single sync.
// =============================================================================
__global__ void __launch_bounds__(256)
score_mma(const __nv_bfloat16* __restrict__ Qh, const __nv_bfloat16* __restrict__ Ql,
          const __nv_bfloat16* __restrict__ Kh, const __nv_bfloat16* __restrict__ Kl,
          float* __restrict__ Pf)
{
    extern __shared__ __align__(16) __nv_bfloat16 smem[];
    __nv_bfloat16* Ah = smem;            // [128][72]
    __nv_bfloat16* Al = smem + 9216;
    __nv_bfloat16* Bh = smem + 18432;
    __nv_bfloat16* Bl = smem + 27648;

    const int tid = threadIdx.x, lane = tid & 31, w = tid >> 5;
    const int wm = w >> 2, wn = w & 3;
    const int bhz = blockIdx.z, b = bhz >> 4, h = bhz & 15;
    const int m0 = blockIdx.y * 128, n0 = blockIdx.x * 128;

    const size_t qbase = (size_t)(b * 1024 + m0) * 1024 + h * 64;
    const size_t kbase = (size_t)(b * 1024 + n0) * 1024 + h * 64;

#pragma unroll
    for (int it = 0; it < 4; it++) {
        int id = tid + it * 256;
        int r = id >> 3, c = (id & 7) * 8;
        cpa16(saddr_of(Ah + r * 72 + c), Qh + qbase + (size_t)r * 1024 + c);
        cpa16(saddr_of(Al + r * 72 + c), Ql + qbase + (size_t)r * 1024 + c);
        cpa16(saddr_of(Bh + r * 72 + c), Kh + kbase + (size_t)r * 1024 + c);
        cpa16(saddr_of(Bl + r * 72 + c), Kl + kbase + (size_t)r * 1024 + c);
    }
    cpa_commit();
    cpa_wait<0>();
    __syncthreads();

    float acc[4][4][4] = {};
#pragma unroll
    for (int ks = 0; ks < 64; ks += 16) {
        uint32_t ah[4][4], al[4][4], bh[4][2], bl[4][2];
#pragma unroll
        for (int mt = 0; mt < 4; mt++) {
            int row = wm * 64 + mt * 16 + (lane & 15);
            int col = ks + ((lane >> 4) << 3);
            ldsm4(ah[mt], saddr_of(Ah + row * 72 + col));
            ldsm4(al[mt], saddr_of(Al + row * 72 + col));
        }
#pragma unroll
        for (int p = 0; p < 2; p++) {
            int row = wn * 32 + p * 16 + ((lane >> 4) << 3) + (lane & 7);
            int col = ks + (((lane >> 3) & 1) << 3);
            uint32_t t4[4];
            ldsm4(t4, saddr_of(Bh + row * 72 + col));
            bh[p * 2][0] = t4[0]; bh[p * 2][1] = t4[1];
            bh[p * 2 + 1][0] = t4[2]; bh[p * 2 + 1][1] = t4[3];
            ldsm4(t4, saddr_of(Bl + row * 72 + col));
            bl[p * 2][0] = t4[0]; bl[p * 2][1] = t4[1];
            bl[p * 2 + 1][0] = t4[2]; bl[p * 2 + 1][1] = t4[3];
        }
#pragma unroll
        for (int mt = 0; mt < 4; mt++)
#pragma unroll
            for (int nt = 0; nt < 4; nt++) {
                mma16816(acc[mt][nt], ah[mt], bh[nt]);
                mma16816(acc[mt][nt], ah[mt], bl[nt]);
                mma16816(acc[mt][nt], al[mt], bh[nt]);
            }
    }

    float* P = Pf + ((size_t)bhz << 20);
    const int gr = lane >> 2, gc = (lane & 3) << 1;
#pragma unroll
    for (int mt = 0; mt < 4; mt++)
#pragma unroll
        for (int nt = 0; nt < 4; nt++) {
            int m = m0 + wm * 64 + mt * 16 + gr;
            int n = n0 + wn * 32 + nt * 8 + gc;
#pragma unroll
            for (int hf = 0; hf < 2; hf++) {
                *(float2*)(P + (size_t)(m + hf * 8) * 1024 + n) =
                    make_float2(acc[mt][nt][hf * 2] * 0.125f, acc[mt][nt][hf * 2 + 1] * 0.125f);
            }
        }
}

// =============================================================================
// K3: row softmax + post-softmax mask + split-bf16 out.
//     Skip writing columns i < (j & ~127): never read by out_mma's tile loop.
// =============================================================================
__global__ void __launch_bounds__(256)
softmax_mask_split(const float* __restrict__ Pf, __nv_bfloat16* __restrict__ Ph,
                   __nv_bfloat16* __restrict__ Pl)
{
    const size_t rid = blockIdx.x;
    const float* p = Pf + (rid << 10);
    const int j = (int)(rid & 1023);
    const int tid = threadIdx.x, lane = tid & 31, wid = tid >> 5;

    float4 v = ((const float4*)p)[tid];

    float lm = fmaxf(fmaxf(v.x, v.y), fmaxf(v.z, v.w));
#pragma unroll
    for (int o = 16; o > 0; o >>= 1) lm = fmaxf(lm, __shfl_xor_sync(0xffffffffu, lm, o));
    __shared__ float sred[8];
    __shared__ float sb;
    if (lane == 0) sred[wid] = lm;
    __syncthreads();
    if (tid == 0) {
        float m = sred[0];
#pragma unroll
        for (int i = 1; i < 8; i++) m = fmaxf(m, sred[i]);
        sb = m;
    }
    __syncthreads();
    const float M = sb;

    v.x = __expf(v.x - M); v.y = __expf(v.y - M);
    v.z = __expf(v.z - M); v.w = __expf(v.w - M);

    float ls = v.x + v.y + v.z + v.w;
#pragma unroll
    for (int o = 16; o > 0; o >>= 1) ls += __shfl_xor_sync(0xffffffffu, ls, o);
    __syncthreads();
    if (lane == 0) sred[wid] = ls;
    __syncthreads();
    if (tid == 0) {
        float s = 0.f;
#pragma unroll
        for (int i = 0; i < 8; i++) s += sred[i];
        sb = 1.f / s;
    }
    __syncthreads();
    const float inv = sb;

    const int i0 = tid * 4;
    if (i0 < (j & ~127)) return;      // out_mma never touches these tiles

    float r[4] = {v.x, v.y, v.z, v.w};
    __nv_bfloat16 h[4], l[4];
#pragma unroll
    for (int e = 0; e < 4; e++) {
        float x = (i0 + e >= j) ? r[e] * inv : 0.f;   // post-softmax triangular mask
        split2(x, h[e], l[e]);
    }
    *(__nv_bfloat162*)(Ph + (rid << 10) + i0)     = __halves2bfloat162(h[0], h[1]);
    *(__nv_bfloat162*)(Ph + (rid << 10) + i0 + 2) = __halves2bfloat162(h[2], h[3]);
    *(__nv_bfloat162*)(Pl + (rid << 10) + i0)     = __halves2bfloat162(l[0], l[1]);
    *(__nv_bfloat162*)(Pl + (rid << 10) + i0 + 2) = __halves2bfloat162(l[2], l[3]);
}

// =============================================================================
// K4: out[i,d] = sum_j P[j,i] * vh[j,d]   (mask already folded into P)
// =============================================================================
__global__ void __launch_bounds__(256)
out_mma(const __nv_bfloat16* __restrict__ Ph, const __nv_bfloat16* __restrict__ Pl,
        const __nv_bfloat16* __restrict__ Vh, const __nv_bfloat16* __restrict__ Vl,
        float* __restrict__ Out)
{
    __shared__ __align__(16) __nv_bfloat16 Psh[32][136];
    __shared__ __align__(16) __nv_bfloat16 Psl[32][136];
    __shared__ __align__(16) __nv_bfloat16 Vsh[32][72];
    __shared__ __align__(16) __nv_bfloat16 Vsl[32][72];

    const int tid = threadIdx.x, lane = tid & 31, w = tid >> 5;
    const int wm = w >> 1, wn = w & 1;
    const int bhz = blockIdx.z, b = bhz >> 4, h = bhz & 15;
    const int i0 = blockIdx.x * 128;

    const __nv_bfloat16* Pbh = Ph + ((size_t)bhz << 20);
    const __nv_bfloat16* Pbl = Pl + ((size_t)bhz << 20);

    float acc[2][4][4] = {};

    const int pr = tid >> 4, pc = tid & 15;
    const int vr = tid >> 3, vc = tid & 7;

    const int jend = i0 + 128;
    for (int j0 = 0; j0 < jend; j0 += 32) {
#pragma unroll
        for (int q = 0; q < 2; q++) {
            int r = pr + q * 16;
            *(uint4*)&Psh[r][pc * 8] = *(const uint4*)(Pbh + (size_t)(j0 + r) * 1024 + i0 + pc * 8);
            *(uint4*)&Psl[r][pc * 8] = *(const uint4*)(Pbl + (size_t)(j0 + r) * 1024 + i0 + pc * 8);
        }
        {
            size_t vb = (size_t)(b * 1024 + j0 + vr) * 1024 + h * 64 + vc * 8;
            *(uint4*)&Vsh[vr][vc * 8] = *(const uint4*)(Vh + vb);
            *(uint4*)&Vsl[vr][vc * 8] = *(const uint4*)(Vl + vb);
        }
        __syncthreads();

#pragma unroll
        for (int ks = 0; ks < 32; ks += 16) {
            uint32_t ah[2][4], al[2][4], bh[4][2], bl[4][2];
#pragma unroll
            for (int mt = 0; mt < 2; mt++) {
                int jr = ks + (lane & 7) + ((lane >> 4) << 3);
                int ic = wm * 32 + mt * 16 + (((lane >> 3) & 1) << 3);
                ldsm4t(ah[mt], saddr_of(&Psh[jr][ic]));
                ldsm4t(al[mt], saddr_of(&Psl[jr][ic]));
            }
#pragma unroll
            for (int p = 0; p < 2; p++) {
                int kr = ks + (((lane >> 3) & 1) << 3) + (lane & 7);
                int dc = wn * 32 + p * 16 + ((lane >> 4) << 3);
                uint32_t t4[4];
                ldsm4t(t4, saddr_of(&Vsh[kr][dc]));
                bh[p * 2][0] = t4[0]; bh[p * 2][1] = t4[1];
                bh[p * 2 + 1][0] = t4[2]; bh[p * 2 + 1][1] = t4[3];
                ldsm4t(t4, saddr_of(&Vsl[kr][dc]));
                bl[p * 2][0] = t4[0]; bl[p * 2][1] = t4[1];
                bl[p * 2 + 1][0] = t4[2]; bl[p * 2 + 1][1] = t4[3];
            }
#pragma unroll
            for (int mt = 0; mt < 2; mt++)
#pragma unroll
                for (int nt = 0; nt < 4; nt++) {
                    mma16816(acc[mt][nt], ah[mt], bh[nt]);
                    mma16816(acc[mt][nt], ah[mt], bl[nt]);
                    mma16816(acc[mt][nt], al[mt], bh[nt]);
                }
        }
        __syncthreads();
    }

    const int gr = lane >> 2, gc = (lane & 3) << 1;
#pragma unroll
    for (int mt = 0; mt < 2; mt++)
#pragma unroll
        for (int nt = 0; nt < 4; nt++) {
            int i = i0 + wm * 32 + mt * 16 + gr;
            int d = wn * 32 + nt * 8 + gc;
#pragma unroll
            for (int hf = 0; hf < 2; hf++) {
                *(float2*)(Out + (size_t)(b * 1024 + i + hf * 8) * 1024 + h * 64 + d) =
                    make_float2(acc[mt][nt][hf * 2], acc[mt][nt][hf * 2 + 1]);
            }
        }
}

// =============================================================================
extern "C" void kernel_launch(void* const* d_in, const int* in_sizes, int n_in,
                              void* d_out, int out_size)
{
    const float* q  = (const float*)d_in[0];
    const float* k  = (const float*)d_in[1];
    const float* v  = (const float*)d_in[2];
    const float* Wq = (const float*)d_in[3];
    const float* Wk = (const float*)d_in[4];
    const float* Wv = (const float*)d_in[5];
    float* out = (float*)d_out;
    (void)in_sizes; (void)n_in; (void)out_size;

    __nv_bfloat16 *xh, *xl, *wh, *wl, *yh, *yl, *ph, *pl;
    float* pf;
    cudaGetSymbolAddress((void**)&xh, g_xh);
    cudaGetSymbolAddress((void**)&xl, g_xl);
    cudaGetSymbolAddress((void**)&wh, g_wh);
    cudaGetSymbolAddress((void**)&wl, g_wl);
    cudaGetSymbolAddress((void**)&yh, g_yh);
    cudaGetSymbolAddress((void**)&yl, g_yl);
    cudaGetSymbolAddress((void**)&pf, g_pf);
    cudaGetSymbolAddress((void**)&ph, g_ph);
    cudaGetSymbolAddress((void**)&pl, g_pl);

    cudaFuncSetAttribute(proj_mma,  cudaFuncAttributeMaxDynamicSharedMemorySize, 81920);
    cudaFuncSetAttribute(score_mma, cudaFuncAttributeMaxDynamicSharedMemorySize, 73728);

    // pre-split inputs to bf16 hi/lo
    split_kernel<<<XN / 1024, 256>>>(q, xh,          xl);
    split_kernel<<<XN / 1024, 256>>>(k, xh + XN,     xl + XN);
    split_kernel<<<XN / 1024, 256>>>(v, xh + 2 * XN, xl + 2 * XN);
    split_kernel<<<WN / 1024, 256>>>(Wq, wh,          wl);
    split_kernel<<<WN / 1024, 256>>>(Wk, wh + WN,     wl + WN);
    split_kernel<<<WN / 1024, 256>>>(Wv, wh + 2 * WN, wl + 2 * WN);

    // all 3 projections in one launch (z = q/k/v)
    proj_mma<<<dim3(8, 64, 3), 256, 81920>>>(xh, xl, wh, wl, yh, yl);

    dim3 sgrid(8, 8, BATCH * NHEADS);
    score_mma<<<sgrid, 256, 73728>>>(yh, yl, yh + XN, yl + XN, pf);

    softmax_mask_split<<<BATCH * NHEADS * SEQ, 256>>>(pf, ph, pl);

    dim3 ogrid(8, 1, BATCH * NHEADS);
    out_mma<<<ogrid, 256>>>(ph, pl, yh + 2 * XN, yl + 2 * XN, out);
}

// round 7
// speedup vs baseline: 2.9959x; 1.0961x over previous
#include <cuda_runtime.h>
#include <cuda_bf16.h>
#include <stdint.h>

#define BATCH 8
#define SEQ 1024
#define HID 1024
#define NHEADS 16
#define DK 64

#define XN 8388608   // 8192*1024
#define WN 1048576   // 1024*1024

// ---------------- scratch (static __device__ — no allocs allowed) -------------
__device__ __align__(16) __nv_bfloat16 g_xh[3 * XN];   // pre-split q,k,v hi
__device__ __align__(16) __nv_bfloat16 g_xl[3 * XN];
__device__ __align__(16) __nv_bfloat16 g_wh[3 * WN];   // pre-split Wq,Wk,Wv hi
__device__ __align__(16) __nv_bfloat16 g_wl[3 * WN];
__device__ __align__(16) __nv_bfloat16 g_yh[3 * XN];   // projected q,k,v hi
__device__ __align__(16) __nv_bfloat16 g_yl[3 * XN];
__device__ __align__(16) __nv_bfloat16 g_ph[134217728];  // E=exp(s/8) masked, hi
__device__ __align__(16) __nv_bfloat16 g_pl[134217728];  // lo
__device__ __align__(16) float g_zp[128 * 1024 * 8];     // per-(bh,row,ntile) partial sums
__device__ __align__(16) float g_zi[128 * 1024];         // 1/Z per (bh,row)
__device__ __align__(16) __nv_bfloat16 g_vph[128 * 65536]; // V' = V/Z, [bh][j][64] hi
__device__ __align__(16) __nv_bfloat16 g_vpl[128 * 65536]; // lo

// ---------------- helpers ----------------------------------------------------
__device__ __forceinline__ uint32_t saddr_of(const void* p) {
    return (uint32_t)__cvta_generic_to_shared(p);
}
__device__ __forceinline__ void cpa16(uint32_t dst, const void* src) {
    asm volatile("cp.async.cg.shared.global [%0], [%1], 16;" :: "r"(dst), "l"(src));
}
__device__ __forceinline__ void cpa_commit() {
    asm volatile("cp.async.commit_group;");
}
template <int N>
__device__ __forceinline__ void cpa_wait() {
    asm volatile("cp.async.wait_group %0;" :: "n"(N));
}
__device__ __forceinline__ void ldsm4(uint32_t r[4], uint32_t a) {
    asm volatile("ldmatrix.sync.aligned.m8n8.x4.shared.b16 {%0,%1,%2,%3}, [%4];"
                 : "=r"(r[0]), "=r"(r[1]), "=r"(r[2]), "=r"(r[3]) : "r"(a));
}
__device__ __forceinline__ void ldsm4t(uint32_t r[4], uint32_t a) {
    asm volatile("ldmatrix.sync.aligned.m8n8.x4.trans.shared.b16 {%0,%1,%2,%3}, [%4];"
                 : "=r"(r[0]), "=r"(r[1]), "=r"(r[2]), "=r"(r[3]) : "r"(a));
}
__device__ __forceinline__ void mma16816(float* c, const uint32_t* a, const uint32_t* b) {
    asm volatile("mma.sync.aligned.m16n8k16.row.col.f32.bf16.bf16.f32 "
                 "{%0,%1,%2,%3}, {%4,%5,%6,%7}, {%8,%9}, {%0,%1,%2,%3};"
                 : "+f"(c[0]), "+f"(c[1]), "+f"(c[2]), "+f"(c[3])
                 : "r"(a[0]), "r"(a[1]), "r"(a[2]), "r"(a[3]), "r"(b[0]), "r"(b[1]));
}
__device__ __forceinline__ void split2(float x, __nv_bfloat16& h, __nv_bfloat16& l) {
    h = __float2bfloat16(x);
    l = __float2bfloat16(x - __bfloat162float(h));
}

// =============================================================================
// K0: elementwise fp32 -> split bf16 hi/lo.
// =============================================================================
__global__ void __launch_bounds__(256)
split_kernel(const float* __restrict__ X, __nv_bfloat16* __restrict__ H,
             __nv_bfloat16* __restrict__ L)
{
    size_t i = ((size_t)blockIdx.x * 256 + threadIdx.x) * 4;
    float4 v = *(const float4*)(X + i);
    __nv_bfloat16 h[4], l[4];
    split2(v.x, h[0], l[0]); split2(v.y, h[1], l[1]);
    split2(v.z, h[2], l[2]); split2(v.w, h[3], l[3]);
    *(__nv_bfloat162*)(H + i)     = __halves2bfloat162(h[0], h[1]);
    *(__nv_bfloat162*)(H + i + 2) = __halves2bfloat162(h[2], h[3]);
    *(__nv_bfloat162*)(L + i)     = __halves2bfloat162(l[0], l[1]);
    *(__nv_bfloat162*)(L + i + 2) = __halves2bfloat162(l[2], l[3]);
}

// =============================================================================
// K1: projection  Y[m,n] = sum_k X[m,k] * W[n,k]  (z = q/k/v), cp.async 2-stage.
// =============================================================================
__global__ void __launch_bounds__(256)
proj_mma(const __nv_bfloat16* __restrict__ Xh, const __nv_bfloat16* __restrict__ Xl,
         const __nv_bfloat16* __restrict__ Wh, const __nv_bfloat16* __restrict__ Wl,
         __nv_bfloat16* __restrict__ Yh, __nv_bfloat16* __restrict__ Yl)
{
    extern __shared__ __align__(16) __nv_bfloat16 smem[];

    const int tid = threadIdx.x, lane = tid & 31, w = tid >> 5;
    const int wm = w >> 2, wn = w & 3;
    const int z = blockIdx.z;
    const size_t xoff = (size_t)z * XN, woff = (size_t)z * WN;
    Xh += xoff; Xl += xoff; Yh += xoff; Yl += xoff; Wh += woff; Wl += woff;
    const int m0 = blockIdx.y * 128, n0 = blockIdx.x * 128;

    const int lr = tid >> 2, lc = (tid & 3) * 8;

    float acc[4][4][4] = {};

#define STG(s, off) (smem + (s) * 20480 + (off))
    auto load_stage = [&](int s, int k0) {
#pragma unroll
        for (int q = 0; q < 2; q++) {
            int r = lr + q * 64;
            cpa16(saddr_of(STG(s, 0)     + r * 40 + lc), Xh + (size_t)(m0 + r) * 1024 + k0 + lc);
            cpa16(saddr_of(STG(s, 5120)  + r * 40 + lc), Xl + (size_t)(m0 + r) * 1024 + k0 + lc);
            cpa16(saddr_of(STG(s, 10240) + r * 40 + lc), Wh + (size_t)(n0 + r) * 1024 + k0 + lc);
            cpa16(saddr_of(STG(s, 15360) + r * 40 + lc), Wl + (size_t)(n0 + r) * 1024 + k0 + lc);
        }
    };

    load_stage(0, 0);
    cpa_commit();

    for (int it = 0; it < 32; it++) {
        const int cur = it & 1;
        if (it + 1 < 32) {
            load_stage(cur ^ 1, (it + 1) * 32);
            cpa_commit();
            cpa_wait<1>();
        } else {
            cpa_wait<0>();
        }
        __syncthreads();

        const __nv_bfloat16* Ah = STG(cur, 0);
        const __nv_bfloat16* Al = STG(cur, 5120);
        const __nv_bfloat16* Bh = STG(cur, 10240);
        const __nv_bfloat16* Bl = STG(cur, 15360);

#pragma unroll
        for (int ks = 0; ks < 32; ks += 16) {
            uint32_t ah[4][4], al[4][4], bh[4][2], bl[4][2];
#pragma unroll
            for (int mt = 0; mt < 4; mt++) {
                int row = wm * 64 + mt * 16 + (lane & 15);
                int col = ks + ((lane >> 4) << 3);
                ldsm4(ah[mt], saddr_of(Ah + row * 40 + col));
                ldsm4(al[mt], saddr_of(Al + row * 40 + col));
            }
#pragma unroll
            for (int p = 0; p < 2; p++) {
                int row = wn * 32 + p * 16 + ((lane >> 4) << 3) + (lane & 7);
                int col = ks + (((lane >> 3) & 1) << 3);
                uint32_t t4[4];
                ldsm4(t4, saddr_of(Bh + row * 40 + col));
                bh[p * 2][0] = t4[0]; bh[p * 2][1] = t4[1];
                bh[p * 2 + 1][0] = t4[2]; bh[p * 2 + 1][1] = t4[3];
                ldsm4(t4, saddr_of(Bl + row * 40 + col));
                bl[p * 2][0] = t4[0]; bl[p * 2][1] = t4[1];
                bl[p * 2 + 1][0] = t4[2]; bl[p * 2 + 1][1] = t4[3];
            }
#pragma unroll
            for (int mt = 0; mt < 4; mt++)
#pragma unroll
                for (int nt = 0; nt < 4; nt++) {
                    mma16816(acc[mt][nt], ah[mt], bh[nt]);
                    mma16816(acc[mt][nt], ah[mt], bl[nt]);
                    mma16816(acc[mt][nt], al[mt], bh[nt]);
                }
        }
        __syncthreads();
    }
#undef STG

    const int gr = lane >> 2, gc = (lane & 3) << 1;
#pragma unroll
    for (int mt = 0; mt < 4; mt++)
#pragma unroll
        for (int nt = 0; nt < 4; nt++) {
            int m = m0 + wm * 64 + mt * 16 + gr;
            int n = n0 + wn * 32 + nt * 8 + gc;
#pragma unroll
            for (int hf = 0; hf < 2; hf++) {
                float c0 = acc[mt][nt][hf * 2], c1 = acc[mt][nt][hf * 2 + 1];
                __nv_bfloat16 h0, l0, h1, l1;
                split2(c0, h0, l0);
                split2(c1, h1, l1);
                size_t off = (size_t)(m + hf * 8) * 1024 + n;
                *(__nv_bfloat162*)(Yh + off) = __halves2bfloat162(h0, h1);
                *(__nv_bfloat162*)(Yl + off) = __halves2bfloat162(l0, l1);
            }
        }
}

// =============================================================================
// K2: score+exp  E[bh, j, i] = exp(0.125 * sum_d q[j,d]*k[i,d])
//     Writes masked E (i>=j) as bf16 hi/lo ONLY when n0 >= m0 (tiles out_mma reads).
//     Writes deterministic per-CTA row-sum partials g_zp[bh][j][n0/128].
// =============================================================================
__global__ void __launch_bounds__(256)
score_mma(const __nv_bfloat16* __restrict__ Qh, const __nv_bfloat16* __restrict__ Ql,
          const __nv_bfloat16* __restrict__ Kh, const __nv_bfloat16* __restrict__ Kl,
          __nv_bfloat16* __restrict__ Eh, __nv_bfloat16* __restrict__ El,
          float* __restrict__ Zp)
{
    extern __shared__ __align__(16) __nv_bfloat16 smem[];
    __nv_bfloat16* Ah = smem;            // [128][72]
    __nv_bfloat16* Al = smem + 9216;
    __nv_bfloat16* Bh = smem + 18432;
    __nv_bfloat16* Bl = smem + 27648;
    __shared__ __align__(16) float srow[128][4];

    const int tid = threadIdx.x, lane = tid & 31, w = tid >> 5;
    const int wm = w >> 2, wn = w & 3;
    const int bhz = blockIdx.z, b = bhz >> 4, h = bhz & 15;
    const int m0 = blockIdx.y * 128, n0 = blockIdx.x * 128;

    const size_t qbase = (size_t)(b * 1024 + m0) * 1024 + h * 64;
    const size_t kbase = (size_t)(b * 1024 + n0) * 1024 + h * 64;

#pragma unroll
    for (int it = 0; it < 4; it++) {
        int id = tid + it * 256;
        int r = id >> 3, c = (id & 7) * 8;
        cpa16(saddr_of(Ah + r * 72 + c), Qh + qbase + (size_t)r * 1024 + c);
        cpa16(saddr_of(Al + r * 72 + c), Ql + qbase + (size_t)r * 1024 + c);
        cpa16(saddr_of(Bh + r * 72 + c), Kh + kbase + (size_t)r * 1024 + c);
        cpa16(saddr_of(Bl + r * 72 + c), Kl + kbase + (size_t)r * 1024 + c);
    }
    cpa_commit();
    cpa_wait<0>();
    __syncthreads();

    float acc[4][4][4] = {};
#pragma unroll
    for (int ks = 0; ks < 64; ks += 16) {
        uint32_t ah[4][4], al[4][4], bh[4][2], bl[4][2];
#pragma unroll
        for (int mt = 0; mt < 4; mt++) {
            int row = wm * 64 + mt * 16 + (lane & 15);
            int col = ks + ((lane >> 4) << 3);
            ldsm4(ah[mt], saddr_of(Ah + row * 72 + col));
            ldsm4(al[mt], saddr_of(Al + row * 72 + col));
        }
#pragma unroll
        for (int p = 0; p < 2; p++) {
            int row = wn * 32 + p * 16 + ((lane >> 4) << 3) + (lane & 7);
            int col = ks + (((lane >> 3) & 1) << 3);
            uint32_t t4[4];
            ldsm4(t4, saddr_of(Bh + row * 72 + col));
            bh[p * 2][0] = t4[0]; bh[p * 2][1] = t4[1];
            bh[p * 2 + 1][0] = t4[2]; bh[p * 2 + 1][1] = t4[3];
            ldsm4(t4, saddr_of(Bl + row * 72 + col));
            bl[p * 2][0] = t4[0]; bl[p * 2][1] = t4[1];
            bl[p * 2 + 1][0] = t4[2]; bl[p * 2 + 1][1] = t4[3];
        }
#pragma unroll
        for (int mt = 0; mt < 4; mt++)
#pragma unroll
            for (int nt = 0; nt < 4; nt++) {
                mma16816(acc[mt][nt], ah[mt], bh[nt]);
                mma16816(acc[mt][nt], ah[mt], bl[nt]);
                mma16816(acc[mt][nt], al[mt], bh[nt]);
            }
    }

    // ---- exponentiate in place: acc <- exp(acc / 8) ----
#pragma unroll
    for (int mt = 0; mt < 4; mt++)
#pragma unroll
        for (int nt = 0; nt < 4; nt++)
#pragma unroll
            for (int q = 0; q < 4; q++)
                acc[mt][nt][q] = __expf(acc[mt][nt][q] * 0.125f);

    const int gr = lane >> 2, gc = (lane & 3) << 1;

    // ---- deterministic row-sum partials ----
#pragma unroll
    for (int mt = 0; mt < 4; mt++) {
        float s_lo = 0.f, s_hi = 0.f;
#pragma unroll
        for (int nt = 0; nt < 4; nt++) {
            s_lo += acc[mt][nt][0] + acc[mt][nt][1];
            s_hi += acc[mt][nt][2] + acc[mt][nt][3];
        }
        // reduce over the 4 lanes of this quad (same row, different cols)
        s_lo += __shfl_xor_sync(0xffffffffu, s_lo, 1);
        s_lo += __shfl_xor_sync(0xffffffffu, s_lo, 2);
        s_hi += __shfl_xor_sync(0xffffffffu, s_hi, 1);
        s_hi += __shfl_xor_sync(0xffffffffu, s_hi, 2);
        if ((lane & 3) == 0) {
            srow[wm * 64 + mt * 16 + gr][wn]     = s_lo;
            srow[wm * 64 + mt * 16 + gr + 8][wn] = s_hi;
        }
    }
    __syncthreads();
    if (tid < 128) {
        float zp = srow[tid][0] + srow[tid][1] + srow[tid][2] + srow[tid][3];
        Zp[((size_t)(bhz << 10) + m0 + tid) * 8 + (n0 >> 7)] = zp;
    }

    // ---- write masked E tile (only tiles out_mma will read) ----
    if (n0 >= m0) {
        __nv_bfloat16* EH = Eh + ((size_t)bhz << 20);
        __nv_bfloat16* EL = El + ((size_t)bhz << 20);
#pragma unroll
        for (int mt = 0; mt < 4; mt++)
#pragma unroll
            for (int nt = 0; nt < 4; nt++) {
                int m = m0 + wm * 64 + mt * 16 + gr;
                int n = n0 + wn * 32 + nt * 8 + gc;
#pragma unroll
                for (int hf = 0; hf < 2; hf++) {
                    int mm = m + hf * 8;
                    float e0 = (n >= mm)     ? acc[mt][nt][hf * 2]     : 0.f;
                    float e1 = (n + 1 >= mm) ? acc[mt][nt][hf * 2 + 1] : 0.f;
                    __nv_bfloat16 h0, l0, h1, l1;
                    split2(e0, h0, l0);
                    split2(e1, h1, l1);
                    size_t off = (size_t)mm * 1024 + n;
                    *(__nv_bfloat162*)(EH + off) = __halves2bfloat162(h0, h1);
                    *(__nv_bfloat162*)(EL + off) = __halves2bfloat162(l0, l1);
                }
            }
    }
}

// =============================================================================
// K3a: invZ[r] = 1 / sum(partials, fixed order)  (deterministic)
// =============================================================================
__global__ void __launch_bounds__(256)
zred_kernel(const float* __restrict__ Zp, float* __restrict__ Zi)
{
    int r = blockIdx.x * 256 + threadIdx.x;   // 0 .. 131071
    const float* p = Zp + (size_t)r * 8;
    float s = 0.f;
#pragma unroll
    for (int t = 0; t < 8; t++) s += p[t];
    Zi[r] = 1.f / s;
}

// =============================================================================
// K3b: V'[bh][j][d] = V[b][j][h*64+d] * invZ[bh][j], split bf16 hi/lo.
//      One warp per (bh, j) row; 2 elems per lane.
// =============================================================================
__global__ void __launch_bounds__(256)
vscale_kernel(const __nv_bfloat16* __restrict__ Vh, const __nv_bfloat16* __restrict__ Vl,
              const float* __restrict__ Zi,
              __nv_bfloat16* __restrict__ Ph, __nv_bfloat16* __restrict__ Pl)
{
    int wid = blockIdx.x * 8 + (threadIdx.x >> 5);   // 0 .. 131071 (bh*1024 + j)
    int lane = threadIdx.x & 31;
    int bh = wid >> 10, j = wid & 1023;
    int b = bh >> 4, h = bh & 15;
    float inv = Zi[wid];

    size_t src = (size_t)(b * 1024 + j) * 1024 + h * 64 + lane * 2;
    __nv_bfloat162 vh2 = *(const __nv_bfloat162*)(Vh + src);
    __nv_bfloat162 vl2 = *(const __nv_bfloat162*)(Vl + src);
    float v0 = (__bfloat162float(__low2bfloat16(vh2)) + __bfloat162float(__low2bfloat16(vl2))) * inv;
    float v1 = (__bfloat162float(__high2bfloat16(vh2)) + __bfloat162float(__high2bfloat16(vl2))) * inv;
    __nv_bfloat16 h0, l0, h1, l1;
    split2(v0, h0, l0);
    split2(v1, h1, l1);
    size_t dst = (size_t)wid * 64 + lane * 2;
    *(__nv_bfloat162*)(Ph + dst) = __halves2bfloat162(h0, h1);
    *(__nv_bfloat162*)(Pl + dst) = __halves2bfloat162(l0, l1);
}

// =============================================================================
// K4: out[i,d] = sum_j E[j,i] * V'[j,d]   (normalization folded into V')
// =============================================================================
__global__ void __launch_bounds__(256)
out_mma(const __nv_bfloat16* __restrict__ Eh, const __nv_bfloat16* __restrict__ El,
        const __nv_bfloat16* __restrict__ Vh, const __nv_bfloat16* __restrict__ Vl,
        float* __restrict__ Out)
{
    __shared__ __align__(16) __nv_bfloat16 Psh[32][136];
    __shared__ __align__(16) __nv_bfloat16 Psl[32][136];
    __shared__ __align__(16) __nv_bfloat16 Vsh[32][72];
    __shared__ __align__(16) __nv_bfloat16 Vsl[32][72];

    const int tid = threadIdx.x, lane = tid & 31, w = tid >> 5;
    const int wm = w >> 1, wn = w & 1;
    const int bhz = blockIdx.z, b = bhz >> 4, h = bhz & 15;
    const int i0 = blockIdx.x * 128;

    const __nv_bfloat16* Pbh = Eh + ((size_t)bhz << 20);
    const __nv_bfloat16* Pbl = El + ((size_t)bhz << 20);
    const __nv_bfloat16* Vbh = Vh + ((size_t)bhz << 16);
    const __nv_bfloat16* Vbl = Vl + ((size_t)bhz << 16);

    float acc[2][4][4] = {};

    const int pr = tid >> 4, pc = tid & 15;
    const int vr = tid >> 3, vc = tid & 7;

    const int jend = i0 + 128;
    for (int j0 = 0; j0 < jend; j0 += 32) {
#pragma unroll
        for (int q = 0; q < 2; q++) {
            int r = pr + q * 16;
            *(uint4*)&Psh[r][pc * 8] = *(const uint4*)(Pbh + (size_t)(j0 + r) * 1024 + i0 + pc * 8);
            *(uint4*)&Psl[r][pc * 8] = *(const uint4*)(Pbl + (size_t)(j0 + r) * 1024 + i0 + pc * 8);
        }
        {
            size_t vb = (size_t)(j0 + vr) * 64 + vc * 8;
            *(uint4*)&Vsh[vr][vc * 8] = *(const uint4*)(Vbh + vb);
            *(uint4*)&Vsl[vr][vc * 8] = *(const uint4*)(Vbl + vb);
        }
        __syncthreads();

#pragma unroll
        for (int ks = 0; ks < 32; ks += 16) {
            uint32_t ah[2][4], al[2][4], bh[4][2], bl[4][2];
#pragma unroll
            for (int mt = 0; mt < 2; mt++) {
                int jr = ks + (lane & 7) + ((lane >> 4) << 3);
                int ic = wm * 32 + mt * 16 + (((lane >> 3) & 1) << 3);
                ldsm4t(ah[mt], saddr_of(&Psh[jr][ic]));
                ldsm4t(al[mt], saddr_of(&Psl[jr][ic]));
            }
#pragma unroll
            for (int p = 0; p < 2; p++) {
                int kr = ks + (((lane >> 3) & 1) << 3) + (lane & 7);
                int dc = wn * 32 + p * 16 + ((lane >> 4) << 3);
                uint32_t t4[4];
                ldsm4t(t4, saddr_of(&Vsh[kr][dc]));
                bh[p * 2][0] = t4[0]; bh[p * 2][1] = t4[1];
                bh[p * 2 + 1][0] = t4[2]; bh[p * 2 + 1][1] = t4[3];
                ldsm4t(t4, saddr_of(&Vsl[kr][dc]));
                bl[p * 2][0] = t4[0]; bl[p * 2][1] = t4[1];
                bl[p * 2 + 1][0] = t4[2]; bl[p * 2 + 1][1] = t4[3];
            }
#pragma unroll
            for (int mt = 0; mt < 2; mt++)
#pragma unroll
                for (int nt = 0; nt < 4; nt++) {
                    mma16816(acc[mt][nt], ah[mt], bh[nt]);
                    mma16816(acc[mt][nt], ah[mt], bl[nt]);
                    mma16816(acc[mt][nt], al[mt], bh[nt]);
                }
        }
        __syncthreads();
    }

    const int gr = lane >> 2, gc = (lane & 3) << 1;
#pragma unroll
    for (int mt = 0; mt < 2; mt++)
#pragma unroll
        for (int nt = 0; nt < 4; nt++) {
            int i = i0 + wm * 32 + mt * 16 + gr;
            int d = wn * 32 + nt * 8 + gc;
#pragma unroll
            for (int hf = 0; hf < 2; hf++) {
                *(float2*)(Out + (size_t)(b * 1024 + i + hf * 8) * 1024 + h * 64 + d) =
                    make_float2(acc[mt][nt][hf * 2], acc[mt][nt][hf * 2 + 1]);
            }
        }
}

// =============================================================================
extern "C" void kernel_launch(void* const* d_in, const int* in_sizes, int n_in,
                              void* d_out, int out_size)
{
    const float* q  = (const float*)d_in[0];
    const float* k  = (const float*)d_in[1];
    const float* v  = (const float*)d_in[2];
    const float* Wq = (const float*)d_in[3];
    const float* Wk = (const float*)d_in[4];
    const float* Wv = (const float*)d_in[5];
    float* out = (float*)d_out;
    (void)in_sizes; (void)n_in; (void)out_size;

    __nv_bfloat16 *xh, *xl, *wh, *wl, *yh, *yl, *ph, *pl, *vph, *vpl;
    float *zp, *zi;
    cudaGetSymbolAddress((void**)&xh, g_xh);
    cudaGetSymbolAddress((void**)&xl, g_xl);
    cudaGetSymbolAddress((void**)&wh, g_wh);
    cudaGetSymbolAddress((void**)&wl, g_wl);
    cudaGetSymbolAddress((void**)&yh, g_yh);
    cudaGetSymbolAddress((void**)&yl, g_yl);
    cudaGetSymbolAddress((void**)&ph, g_ph);
    cudaGetSymbolAddress((void**)&pl, g_pl);
    cudaGetSymbolAddress((void**)&zp, g_zp);
    cudaGetSymbolAddress((void**)&zi, g_zi);
    cudaGetSymbolAddress((void**)&vph, g_vph);
    cudaGetSymbolAddress((void**)&vpl, g_vpl);

    cudaFuncSetAttribute(proj_mma,  cudaFuncAttributeMaxDynamicSharedMemorySize, 81920);
    cudaFuncSetAttribute(score_mma, cudaFuncAttributeMaxDynamicSharedMemorySize, 73728);

    // pre-split inputs to bf16 hi/lo
    split_kernel<<<XN / 1024, 256>>>(q, xh,          xl);
    split_kernel<<<XN / 1024, 256>>>(k, xh + XN,     xl + XN);
    split_kernel<<<XN / 1024, 256>>>(v, xh + 2 * XN, xl + 2 * XN);
    split_kernel<<<WN / 1024, 256>>>(Wq, wh,          wl);
    split_kernel<<<WN / 1024, 256>>>(Wk, wh + WN,     wl + WN);
    split_kernel<<<WN / 1024, 256>>>(Wv, wh + 2 * WN, wl + 2 * WN);

    // all 3 projections in one launch (z = q/k/v)
    proj_mma<<<dim3(8, 64, 3), 256, 81920>>>(xh, xl, wh, wl, yh, yl);

    // fused score + exp + masked-E write + row-sum partials
    dim3 sgrid(8, 8, BATCH * NHEADS);
    score_mma<<<sgrid, 256, 73728>>>(yh, yl, yh + XN, yl + XN, ph, pl, zp);

    // invZ, then fold into V'
    zred_kernel<<<512, 256>>>(zp, zi);
    vscale_kernel<<<16384, 256>>>(yh + 2 * XN, yl + 2 * XN, zi, vph, vpl);

    dim3 ogrid(8, 1, BATCH * NHEADS);
    out_mma<<<ogrid, 256>>>(ph, pl, vph, vpl, out);
}